// round 5
// baseline (speedup 1.0000x reference)
#include <cuda_runtime.h>
#include <cuda_bf16.h>

#define BATCH 2048
#define NCLS  50257
#define KLBL  20
#define TPB   512
#define CMID  25128            // chunk split point (multiple of 8)
#define NBLK  (BATCH * 2)

// Scratch (no cudaMalloc allowed)
__device__ float g_part[BATCH * 2];   // per-(row,chunk) softplus partial (chunk0 has -corr folded in)
__device__ float g_aux [BATCH];       // pos_mean per row
__device__ float g_cnt [BATCH];       // NCLS - U per row
__device__ int   g_counter = 0;       // last-block election; reset by last block

// ---------------------------------------------------------------------------
// MUFU-free exp(x). Valid (mod-2^32-exact exponent construction) to |x|~87;
// product-chain overflow safety needs |x|<22; data is N(0,1), max |x|~6.1.
// deg-4 Taylor on t in [-0.347,0.347]: rel err <= t^5/120 ~ 4.2e-5.
// ---------------------------------------------------------------------------
__device__ __forceinline__ float exp_fast(float x)
{
    float z  = fmaf(x, 1.4426950408889634f, 12582912.0f);   // magic: 1.5*2^23
    float nf = z - 12582912.0f;                             // rint(x*log2e)
    float t  = fmaf(nf, -0.6931471805599453f, x);
    float p;
    p = fmaf(t, 0.041666667f, 0.16666667f);
    p = fmaf(p, t, 0.5f);
    p = fmaf(p, t, 1.0f);
    p = fmaf(p, t, 1.0f);
    int sbits = (__float_as_int(z) << 23) + 0x3F800000;     // 2^n (wraps exactly)
    return p * __int_as_float(sbits);
}

__device__ __forceinline__ void renorm(float& P, int& E)
{
    int b = __float_as_int(P);
    E += (b >> 23) - 127;
    P  = __int_as_float((b & 0x007FFFFF) | 0x3F800000);     // mantissa in [1,2)
}

// ---------------------------------------------------------------------------
// One block per (row, chunk). chunk0 also does the label pass.
// The very last block to finish combines everything -> scalar output.
// ---------------------------------------------------------------------------
__global__ __launch_bounds__(TPB)
void fused_row(const float* __restrict__ in, const int* __restrict__ tgt,
               float* __restrict__ out)
{
    const int bid = blockIdx.x;
    const int row = bid >> 1;
    const int s   = bid & 1;
    const int tid = threadIdx.x;
    const int c0  = s ? CMID : 0;
    const int c1  = s ? NCLS : CMID;
    const float* p = in + (size_t)row * NCLS;

    __shared__ float sbuf[TPB];
    __shared__ int   slab[KLBL];
    __shared__ int   isLast;

    // --- label gathers (chunk 0 only), issued early to hide under the stream ---
    float xlab = 0.0f;
    int   mylab = -1;
    if (s == 0) {
        if (tid < KLBL) slab[tid] = tgt[row * KLBL + tid];
        __syncthreads();
        if (tid < KLBL) { mylab = slab[tid]; xlab = __ldg(p + mylab); }
    }

    // --- streaming product over [c0, c1) ---
    float Pa = 1.0f, Pb = 1.0f;
    int   Ea = 0,   Eb = 0;

    // (row*NCLS + c0) mod 4 == (row + c0) mod 4  since NCLS % 4 == 1
    const int h = (4 - ((row + c0) & 3)) & 3;
    if (tid < h) { Pa = fmaf(exp_fast(p[c0 + tid]), Pa, Pa); renorm(Pa, Ea); }

    const int n4 = (c1 - c0 - h) >> 2;
    const float4* v = (const float4*)(p + c0 + h);

    int i = tid;
    for (; i + TPB < n4; i += 2 * TPB) {
        float4 xa = v[i];
        float4 xb = v[i + TPB];
        Pa = fmaf(exp_fast(xa.x), Pa, Pa);
        Pa = fmaf(exp_fast(xa.y), Pa, Pa);
        Pb = fmaf(exp_fast(xa.z), Pb, Pb);
        Pb = fmaf(exp_fast(xa.w), Pb, Pb);
        Pa = fmaf(exp_fast(xb.x), Pa, Pa);
        Pa = fmaf(exp_fast(xb.y), Pa, Pa);
        Pb = fmaf(exp_fast(xb.z), Pb, Pb);
        Pb = fmaf(exp_fast(xb.w), Pb, Pb);
        renorm(Pa, Ea);
        renorm(Pb, Eb);
    }
    if (i < n4) {
        float4 xa = v[i];
        Pa = fmaf(exp_fast(xa.x), Pa, Pa);
        Pa = fmaf(exp_fast(xa.y), Pa, Pa);
        Pb = fmaf(exp_fast(xa.z), Pb, Pb);
        Pb = fmaf(exp_fast(xa.w), Pb, Pb);
        renorm(Pa, Ea);
        renorm(Pb, Eb);
    }
    const int t0 = c0 + h + (n4 << 2);
    if (tid < c1 - t0) {
        Pa = fmaf(exp_fast(p[t0 + tid]), Pa, Pa);
        renorm(Pa, Ea);
    }

    float val = fmaf((float)(Ea + Eb), 0.69314718055994531f, __logf(Pa * Pb));

    sbuf[tid] = val;
    __syncthreads();
    #pragma unroll
    for (int r = TPB / 2; r > 0; r >>= 1) {
        if (tid < r) sbuf[tid] += sbuf[tid + r];
        __syncthreads();
    }

    // --- emit partials ---
    if (s == 0) {
        // warp 0: label pass (accurate math on 20 elements)
        if (tid < 32) {
            float pos = 0.0f, corr = 0.0f;
            int   U = 0;
            if (tid < KLBL) {
                float x  = xlab;
                float l1 = log1pf(__expf(-fabsf(x)));
                pos = -(fmaxf(-x, 0.0f) + l1);               // log_sigmoid(x)
                bool uniq = true;
                #pragma unroll
                for (int j = 0; j < KLBL; j++)
                    if (j < tid && slab[j] == mylab) uniq = false;
                if (uniq) { corr = fmaxf(x, 0.0f) + l1; U = 1; }  // softplus(x)
            }
            #pragma unroll
            for (int o = 16; o > 0; o >>= 1) {
                pos  += __shfl_down_sync(0xFFFFFFFF, pos,  o);
                corr += __shfl_down_sync(0xFFFFFFFF, corr, o);
                U    += __shfl_down_sync(0xFFFFFFFF, U,    o);
            }
            if (tid == 0) {
                g_part[2 * row]     = sbuf[0] - corr;
                g_aux[row]          = pos * (1.0f / (float)KLBL);
                g_cnt[row]          = (float)(NCLS - U);
            }
        }
    } else if (tid == 0) {
        g_part[2 * row + 1] = sbuf[0];
    }

    // --- last-block election + deterministic final combine ---
    if (tid == 0) {
        __threadfence();
        int t = atomicAdd(&g_counter, 1);
        isLast = (t == NBLK - 1);
    }
    __syncthreads();
    if (isLast) {
        float acc = 0.0f;
        for (int r = tid; r < BATCH; r += TPB) {
            float S = g_part[2 * r] + g_part[2 * r + 1];
            acc += g_aux[r] - S / g_cnt[r];
        }
        __syncthreads();            // sbuf reuse
        sbuf[tid] = acc;
        __syncthreads();
        #pragma unroll
        for (int r = TPB / 2; r > 0; r >>= 1) {
            if (tid < r) sbuf[tid] += sbuf[tid + r];
            __syncthreads();
        }
        if (tid == 0) {
            out[0] = -sbuf[0] / (float)BATCH;
            g_counter = 0;          // reset for next graph replay
        }
    }
}

extern "C" void kernel_launch(void* const* d_in, const int* in_sizes, int n_in,
                              void* d_out, int out_size)
{
    const float* inputs  = (const float*)d_in[0];
    const int*   targets = (const int*)d_in[1];
    float*       out     = (float*)d_out;

    fused_row<<<NBLK, TPB>>>(inputs, targets, out);
}